// round 1
// baseline (speedup 1.0000x reference)
#include <cuda_runtime.h>
#include <math.h>

#define S_LEN 4096
#define NB 8
#define DIN 256
#define DH 512
#define NCH (NB * DH)          /* 4096 channels */
#define MROWS (NB * S_LEN)     /* 32768 gemm rows */

/* Gate scratch, time-major [S][B*H] so the scan reads coalesced. 64 MB each. */
__device__ float g_gi[S_LEN * NCH];
__device__ float g_gf[S_LEN * NCH];
__device__ float g_go[S_LEN * NCH];
__device__ float g_gz[S_LEN * NCH];

#define BM 128
#define BN 64
#define BK 16
#define TM 8
#define TN 4

__global__ __launch_bounds__(256) void gate_gemm_kernel(
    const float* __restrict__ x,
    const float* __restrict__ Wi, const float* __restrict__ bi,
    const float* __restrict__ Wf, const float* __restrict__ bf,
    const float* __restrict__ Wo, const float* __restrict__ bo,
    const float* __restrict__ Wz, const float* __restrict__ bz)
{
    __shared__ float As[BK][BM + 4];   /* transposed A tile, padded (16B-aligned rows) */
    __shared__ float Bs[BK][BN + 4];

    const int g = blockIdx.z;
    const float* W;
    const float* bias;
    float* out;
    switch (g) {
        case 0:  W = Wi; bias = bi; out = g_gi; break;
        case 1:  W = Wf; bias = bf; out = g_gf; break;
        case 2:  W = Wo; bias = bo; out = g_go; break;
        default: W = Wz; bias = bz; out = g_gz; break;
    }

    const int row0 = blockIdx.y * BM;
    const int col0 = blockIdx.x * BN;
    const int tid  = threadIdx.x;
    const int tx   = tid & 15;   /* n micro-tile index */
    const int ty   = tid >> 4;   /* m micro-tile index */

    /* A load mapping: each thread loads 2 float4 (rows arow, arow+64; 4 k's) */
    const int arow = tid >> 2;         /* 0..63 */
    const int ak   = (tid & 3) * 4;    /* 0,4,8,12 */
    /* B load mapping: 1 float4 */
    const int brow = tid >> 4;         /* 0..15 */
    const int bcol = (tid & 15) * 4;   /* 0..60 */

    float acc[TM][TN];
#pragma unroll
    for (int i = 0; i < TM; i++)
#pragma unroll
        for (int j = 0; j < TN; j++) acc[i][j] = 0.f;

    for (int k0 = 0; k0 < DIN; k0 += BK) {
        float4 a0 = *(const float4*)&x[(size_t)(row0 + arow) * DIN + k0 + ak];
        float4 a1 = *(const float4*)&x[(size_t)(row0 + arow + 64) * DIN + k0 + ak];
        float4 bv = *(const float4*)&W[(size_t)(k0 + brow) * DH + col0 + bcol];

        __syncthreads();   /* previous iter's smem reads done before overwrite */

        As[ak + 0][arow] = a0.x;
        As[ak + 1][arow] = a0.y;
        As[ak + 2][arow] = a0.z;
        As[ak + 3][arow] = a0.w;
        As[ak + 0][arow + 64] = a1.x;
        As[ak + 1][arow + 64] = a1.y;
        As[ak + 2][arow + 64] = a1.z;
        As[ak + 3][arow + 64] = a1.w;
        *(float4*)&Bs[brow][bcol] = bv;

        __syncthreads();

#pragma unroll
        for (int k = 0; k < BK; k++) {
            float4 aA = *(float4*)&As[k][ty * TM];
            float4 aB = *(float4*)&As[k][ty * TM + 4];
            float4 bB = *(float4*)&Bs[k][tx * TN];
            float am[TM] = {aA.x, aA.y, aA.z, aA.w, aB.x, aB.y, aB.z, aB.w};
            float bn[TN] = {bB.x, bB.y, bB.z, bB.w};
#pragma unroll
            for (int i = 0; i < TM; i++)
#pragma unroll
                for (int j = 0; j < TN; j++)
                    acc[i][j] = fmaf(am[i], bn[j], acc[i][j]);
        }
    }

    /* Epilogue: bias + activation, write time-major gates[s][b*DH + n] */
#pragma unroll
    for (int i = 0; i < TM; i++) {
        int r = row0 + ty * TM + i;
        int b = r >> 12;        /* r / 4096 */
        int s = r & 4095;
        size_t base = (size_t)s * NCH + (size_t)b * DH;
#pragma unroll
        for (int j = 0; j < TN; j++) {
            int n = col0 + tx * TN + j;
            float v = acc[i][j] + bias[n];
            float res;
            if (g <= 1) {
                /* exp(clip(v, -20, 0)) */
                res = __expf(fminf(fmaxf(v, -20.f), 0.f));
            } else if (g == 2) {
                /* sigmoid */
                res = 1.f / (1.f + __expf(-v));
            } else {
                res = tanhf(v);
            }
            out[base + n] = res;
        }
    }
}

__global__ __launch_bounds__(32) void scan_kernel(float* __restrict__ out)
{
    int ch = blockIdx.x * 32 + threadIdx.x;   /* 0..4095 */
    int b  = ch >> 9;                          /* / 512 */
    int h  = ch & 511;

    const float* pi = g_gi + ch;
    const float* pf = g_gf + ch;
    const float* po = g_go + ch;
    const float* pz = g_gz + ch;
    float* op = out + (size_t)b * S_LEN * DH + h;

    float c = 0.f, n = 1.f;

#pragma unroll 1
    for (int t = 0; t < S_LEN; t += 8) {
        float iv[8], fv[8], ov[8], zv[8];
#pragma unroll
        for (int u = 0; u < 8; u++) {
            size_t idx = (size_t)(t + u) * NCH;
            iv[u] = pi[idx];
            fv[u] = pf[idx];
            ov[u] = po[idx];
            zv[u] = pz[idx];
        }
#pragma unroll
        for (int u = 0; u < 8; u++) {
            c = fmaf(fv[u], c, iv[u] * zv[u]);
            n = fmaf(fv[u], n, iv[u]);
            op[(size_t)(t + u) * DH] = ov[u] * c / (n + 1e-6f);
        }
    }
}

extern "C" void kernel_launch(void* const* d_in, const int* in_sizes, int n_in,
                              void* d_out, int out_size)
{
    const float* x  = (const float*)d_in[0];
    const float* Wi = (const float*)d_in[1];
    const float* bi = (const float*)d_in[2];
    const float* Wf = (const float*)d_in[3];
    const float* bf = (const float*)d_in[4];
    const float* Wo = (const float*)d_in[5];
    const float* bo = (const float*)d_in[6];
    const float* Wz = (const float*)d_in[7];
    const float* bz = (const float*)d_in[8];
    float* out = (float*)d_out;

    dim3 grid(DH / BN, MROWS / BM, 4);
    gate_gemm_kernel<<<grid, 256>>>(x, Wi, bi, Wf, bf, Wo, bo, Wz, bz);
    scan_kernel<<<NCH / 32, 32>>>(out);
}

// round 2
// speedup vs baseline: 1.4540x; 1.4540x over previous
#include <cuda_runtime.h>
#include <math.h>

#define S_LEN 4096
#define NB 8
#define DIN 256
#define DH 512
#define NCH (NB * DH)          /* 4096 channels */
#define MROWS (NB * S_LEN)     /* 32768 gemm rows */

#define TSEG 64
#define NSEG (S_LEN / TSEG)    /* 64 segments */

/* Gate scratch, time-major [S][B*H] so the scan reads coalesced. 64 MB each. */
__device__ float g_gi[S_LEN * NCH];
__device__ float g_gf[S_LEN * NCH];
__device__ float g_go[S_LEN * NCH];
__device__ float g_gz[S_LEN * NCH];

/* Segment aggregates / starts: [NSEG][NCH] */
__device__ float g_A [NSEG * NCH];
__device__ float g_Bc[NSEG * NCH];
__device__ float g_Bn[NSEG * NCH];
__device__ float g_Cs[NSEG * NCH];
__device__ float g_Ns[NSEG * NCH];

#define BM 128
#define BN 64
#define BK 16
#define TM 8
#define TN 4

__global__ __launch_bounds__(256) void gate_gemm_kernel(
    const float* __restrict__ x,
    const float* __restrict__ Wi, const float* __restrict__ bi,
    const float* __restrict__ Wf, const float* __restrict__ bf,
    const float* __restrict__ Wo, const float* __restrict__ bo,
    const float* __restrict__ Wz, const float* __restrict__ bz)
{
    __shared__ float As[BK][BM + 4];
    __shared__ float Bs[BK][BN + 4];

    const int g = blockIdx.z;
    const float* W;
    const float* bias;
    float* out;
    switch (g) {
        case 0:  W = Wi; bias = bi; out = g_gi; break;
        case 1:  W = Wf; bias = bf; out = g_gf; break;
        case 2:  W = Wo; bias = bo; out = g_go; break;
        default: W = Wz; bias = bz; out = g_gz; break;
    }

    const int row0 = blockIdx.y * BM;
    const int col0 = blockIdx.x * BN;
    const int tid  = threadIdx.x;
    const int tx   = tid & 15;
    const int ty   = tid >> 4;

    const int arow = tid >> 2;
    const int ak   = (tid & 3) * 4;
    const int brow = tid >> 4;
    const int bcol = (tid & 15) * 4;

    float acc[TM][TN];
#pragma unroll
    for (int i = 0; i < TM; i++)
#pragma unroll
        for (int j = 0; j < TN; j++) acc[i][j] = 0.f;

    for (int k0 = 0; k0 < DIN; k0 += BK) {
        float4 a0 = *(const float4*)&x[(size_t)(row0 + arow) * DIN + k0 + ak];
        float4 a1 = *(const float4*)&x[(size_t)(row0 + arow + 64) * DIN + k0 + ak];
        float4 bv = *(const float4*)&W[(size_t)(k0 + brow) * DH + col0 + bcol];

        __syncthreads();

        As[ak + 0][arow] = a0.x;
        As[ak + 1][arow] = a0.y;
        As[ak + 2][arow] = a0.z;
        As[ak + 3][arow] = a0.w;
        As[ak + 0][arow + 64] = a1.x;
        As[ak + 1][arow + 64] = a1.y;
        As[ak + 2][arow + 64] = a1.z;
        As[ak + 3][arow + 64] = a1.w;
        *(float4*)&Bs[brow][bcol] = bv;

        __syncthreads();

#pragma unroll
        for (int k = 0; k < BK; k++) {
            float4 aA = *(float4*)&As[k][ty * TM];
            float4 aB = *(float4*)&As[k][ty * TM + 4];
            float4 bB = *(float4*)&Bs[k][tx * TN];
            float am[TM] = {aA.x, aA.y, aA.z, aA.w, aB.x, aB.y, aB.z, aB.w};
            float bn[TN] = {bB.x, bB.y, bB.z, bB.w};
#pragma unroll
            for (int i = 0; i < TM; i++)
#pragma unroll
                for (int j = 0; j < TN; j++)
                    acc[i][j] = fmaf(am[i], bn[j], acc[i][j]);
        }
    }

#pragma unroll
    for (int i = 0; i < TM; i++) {
        int r = row0 + ty * TM + i;
        int b = r >> 12;
        int s = r & 4095;
        size_t base = (size_t)s * NCH + (size_t)b * DH;
#pragma unroll
        for (int j = 0; j < TN; j++) {
            int n = col0 + tx * TN + j;
            float v = acc[i][j] + bias[n];
            float res;
            if (g <= 1) {
                res = __expf(fminf(fmaxf(v, -20.f), 0.f));
            } else if (g == 2) {
                res = 1.f / (1.f + __expf(-v));
            } else {
                res = tanhf(v);
            }
            out[base + n] = res;
        }
    }
}

/* Pass A: per (channel, segment) aggregates.
 * c_end = A*c_start + Bc ; n_end = A*n_start + Bn  (same A = prod f). */
__global__ __launch_bounds__(128) void scan_passA()
{
    const int ch  = blockIdx.x * 128 + threadIdx.x;
    const int seg = blockIdx.y;
    const size_t off = (size_t)seg * TSEG * NCH + ch;
    const float* pf = g_gf + off;
    const float* pi = g_gi + off;
    const float* pz = g_gz + off;

    float A = 1.f, Bc = 0.f, Bn = 0.f;
#pragma unroll 1
    for (int t = 0; t < TSEG; t += 8) {
        float fv[8], iv[8], zv[8];
#pragma unroll
        for (int u = 0; u < 8; u++) {
            size_t idx = (size_t)(t + u) * NCH;
            fv[u] = pf[idx];
            iv[u] = pi[idx];
            zv[u] = pz[idx];
        }
#pragma unroll
        for (int u = 0; u < 8; u++) {
            Bc = fmaf(fv[u], Bc, iv[u] * zv[u]);
            Bn = fmaf(fv[u], Bn, iv[u]);
            A  = A * fv[u];
        }
    }
    g_A [(size_t)seg * NCH + ch] = A;
    g_Bc[(size_t)seg * NCH + ch] = Bc;
    g_Bn[(size_t)seg * NCH + ch] = Bn;
}

/* Pass B: sequential combine across segments (per channel). */
__global__ __launch_bounds__(128) void scan_passB()
{
    const int ch = blockIdx.x * 128 + threadIdx.x;
    float c = 0.f, n = 1.f;
#pragma unroll 1
    for (int s = 0; s < NSEG; s++) {
        size_t idx = (size_t)s * NCH + ch;
        g_Cs[idx] = c;
        g_Ns[idx] = n;
        float A  = g_A[idx];
        float Bc = g_Bc[idx];
        float Bn = g_Bn[idx];
        c = fmaf(A, c, Bc);
        n = fmaf(A, n, Bn);
    }
}

/* Pass C: re-walk each segment from its known start state, emit h. */
__global__ __launch_bounds__(128) void scan_passC(float* __restrict__ out)
{
    const int ch  = blockIdx.x * 128 + threadIdx.x;
    const int seg = blockIdx.y;
    const int b = ch >> 9;
    const int h = ch & 511;

    const size_t off = (size_t)seg * TSEG * NCH + ch;
    const float* pf = g_gf + off;
    const float* pi = g_gi + off;
    const float* po = g_go + off;
    const float* pz = g_gz + off;
    float* op = out + ((size_t)b * S_LEN + (size_t)seg * TSEG) * DH + h;

    size_t sidx = (size_t)seg * NCH + ch;
    float c = g_Cs[sidx];
    float n = g_Ns[sidx];

#pragma unroll 1
    for (int t = 0; t < TSEG; t += 8) {
        float fv[8], iv[8], ov[8], zv[8];
#pragma unroll
        for (int u = 0; u < 8; u++) {
            size_t idx = (size_t)(t + u) * NCH;
            fv[u] = pf[idx];
            iv[u] = pi[idx];
            ov[u] = po[idx];
            zv[u] = pz[idx];
        }
#pragma unroll
        for (int u = 0; u < 8; u++) {
            c = fmaf(fv[u], c, iv[u] * zv[u]);
            n = fmaf(fv[u], n, iv[u]);
            op[(size_t)(t + u) * DH] = ov[u] * c / (n + 1e-6f);
        }
    }
}

extern "C" void kernel_launch(void* const* d_in, const int* in_sizes, int n_in,
                              void* d_out, int out_size)
{
    const float* x  = (const float*)d_in[0];
    const float* Wi = (const float*)d_in[1];
    const float* bi = (const float*)d_in[2];
    const float* Wf = (const float*)d_in[3];
    const float* bf = (const float*)d_in[4];
    const float* Wo = (const float*)d_in[5];
    const float* bo = (const float*)d_in[6];
    const float* Wz = (const float*)d_in[7];
    const float* bz = (const float*)d_in[8];
    float* out = (float*)d_out;

    dim3 grid(DH / BN, MROWS / BM, 4);
    gate_gemm_kernel<<<grid, 256>>>(x, Wi, bi, Wf, bf, Wo, bo, Wz, bz);

    dim3 gA(NCH / 128, NSEG);
    scan_passA<<<gA, 128>>>();
    scan_passB<<<NCH / 128, 128>>>();
    scan_passC<<<gA, 128>>>(out);
}

// round 4
// speedup vs baseline: 2.3202x; 1.5957x over previous
#include <cuda_runtime.h>
#include <cuda_bf16.h>
#include <cstdint>
#include <math.h>

#define S_LEN 4096
#define NB 8
#define DIN 256
#define DH 512
#define NCH (NB * DH)          /* 4096 channels */
#define MROWS (NB * S_LEN)     /* 32768 gemm rows */
#define NTOT (4 * DH)          /* 2048 concat N */

#define TSEG 64
#define NSEG (S_LEN / TSEG)

/* Gate scratch, time-major [S][B*H]. 64 MB each. */
__device__ float g_gi[S_LEN * NCH];
__device__ float g_gf[S_LEN * NCH];
__device__ float g_go[S_LEN * NCH];
__device__ float g_gz[S_LEN * NCH];

/* Segment aggregates / starts */
__device__ float g_A [NSEG * NCH];
__device__ float g_Bc[NSEG * NCH];
__device__ float g_Bn[NSEG * NCH];
__device__ float g_Cs[NSEG * NCH];
__device__ float g_Ns[NSEG * NCH];

/* bf16 split operands */
__device__ __nv_bfloat16 g_xhi[(size_t)MROWS * DIN];
__device__ __nv_bfloat16 g_xlo[(size_t)MROWS * DIN];
__device__ __nv_bfloat16 g_wthi[(size_t)NTOT * DIN];   /* transposed: [n_global][k] */
__device__ __nv_bfloat16 g_wtlo[(size_t)NTOT * DIN];

/* ------------------------------------------------------------------ */
__device__ __forceinline__ uint32_t smem_u32(const void* p) {
    uint32_t a;
    asm("{ .reg .u64 t; cvta.to.shared.u64 t, %1; cvt.u32.u64 %0, t; }" : "=r"(a) : "l"(p));
    return a;
}
__device__ __forceinline__ void cp_async16(uint32_t saddr, const void* g) {
    asm volatile("cp.async.cg.shared.global [%0], [%1], 16;" :: "r"(saddr), "l"(g));
}
__device__ __forceinline__ void cp_commit() {
    asm volatile("cp.async.commit_group;");
}
__device__ __forceinline__ void cp_wait0() {
    asm volatile("cp.async.wait_group 0;");
}
__device__ __forceinline__ void ldm_x4(uint32_t& r0, uint32_t& r1, uint32_t& r2, uint32_t& r3,
                                       uint32_t addr) {
    asm volatile("ldmatrix.sync.aligned.m8n8.x4.shared.b16 {%0,%1,%2,%3}, [%4];"
                 : "=r"(r0), "=r"(r1), "=r"(r2), "=r"(r3) : "r"(addr));
}
__device__ __forceinline__ void mma16816(float* c, const uint32_t* a, const uint32_t* b) {
    asm volatile(
        "mma.sync.aligned.m16n8k16.row.col.f32.bf16.bf16.f32 "
        "{%0,%1,%2,%3}, {%4,%5,%6,%7}, {%8,%9}, {%0,%1,%2,%3};"
        : "+f"(c[0]), "+f"(c[1]), "+f"(c[2]), "+f"(c[3])
        : "r"(a[0]), "r"(a[1]), "r"(a[2]), "r"(a[3]), "r"(b[0]), "r"(b[1]));
}

/* ------------------------------------------------------------------ */
/* Conversion kernels                                                  */
/* ------------------------------------------------------------------ */
__global__ __launch_bounds__(256) void convert_x(const float* __restrict__ x)
{
    size_t i = ((size_t)blockIdx.x * 256 + threadIdx.x) * 4;
    float4 v = *(const float4*)(x + i);
    float vv[4] = {v.x, v.y, v.z, v.w};
#pragma unroll
    for (int j = 0; j < 4; j++) {
        __nv_bfloat16 h = __float2bfloat16_rn(vv[j]);
        g_xhi[i + j] = h;
        g_xlo[i + j] = __float2bfloat16_rn(vv[j] - __bfloat162float(h));
    }
}

__global__ void convert_w(const float* __restrict__ Wi, const float* __restrict__ Wf,
                          const float* __restrict__ Wo, const float* __restrict__ Wz)
{
    const float* W = (blockIdx.z == 0) ? Wi : (blockIdx.z == 1) ? Wf
                   : (blockIdx.z == 2) ? Wo : Wz;
    __shared__ float t[32][33];
    int k0 = blockIdx.x * 32, n0 = blockIdx.y * 32;
    int tx = threadIdx.x, ty = threadIdx.y;    /* (32,8) */
#pragma unroll
    for (int j = 0; j < 4; j++)
        t[ty * 4 + j][tx] = W[(size_t)(k0 + ty * 4 + j) * DH + n0 + tx];
    __syncthreads();
#pragma unroll
    for (int j = 0; j < 4; j++) {
        float v = t[tx][ty * 4 + j];           /* k = k0+tx, n = n0+ty*4+j */
        size_t o = (size_t)(blockIdx.z * DH + n0 + ty * 4 + j) * DIN + k0 + tx;
        __nv_bfloat16 h = __float2bfloat16_rn(v);
        g_wthi[o] = h;
        g_wtlo[o] = __float2bfloat16_rn(v - __bfloat162float(h));
    }
}

/* ------------------------------------------------------------------ */
/* HMMA GEMM: [32768 x 256] x [256 x 2048], 3-term bf16 split          */
/* BM=128 BN=128 BK=32, 8 warps, warp tile 64x32, double buffered      */
/* ------------------------------------------------------------------ */
#define LDS 40                 /* smem row stride in halves (padded) */
#define NVK 24                 /* 3 terms x 8 k-chunks */

__global__ __launch_bounds__(256) void gemm_hmma(
    const float* __restrict__ bi, const float* __restrict__ bfp,
    const float* __restrict__ bo, const float* __restrict__ bz)
{
    __shared__ __align__(16) __nv_bfloat16 sA[2][128 * LDS];
    __shared__ __align__(16) __nv_bfloat16 sB[2][128 * LDS];

    const int tid  = threadIdx.x;
    const int lane = tid & 31;
    const int w    = tid >> 5;
    const int wm   = w & 1;          /* warp m index (0..1)  -> 64 rows  */
    const int wn   = w >> 1;         /* warp n index (0..3)  -> 32 cols  */

    const int m0 = blockIdx.y * 128;
    const int n0 = blockIdx.x * 128; /* global concat-n */

    const __nv_bfloat16* Asrc[3] = {g_xhi,  g_xhi,  g_xlo };
    const __nv_bfloat16* Bsrc[3] = {g_wthi, g_wtlo, g_wthi};

    const uint32_t sA0 = smem_u32(sA);
    const uint32_t sB0 = smem_u32(sB);
    const uint32_t bufBytes = 128 * LDS * 2;

    /* each thread copies 2 x 16B chunks of A and of B per stage */
    const int c0row = tid >> 1;                 /* chunk pair: rows tid>>1, +? */
    /* chunk id c in [0,512): row=c>>2, k16=c&3. thread handles c=tid, tid+256 */

    float acc[4][4][4];
#pragma unroll
    for (int i = 0; i < 4; i++)
#pragma unroll
        for (int j = 0; j < 4; j++)
#pragma unroll
            for (int e = 0; e < 4; e++) acc[i][j][e] = 0.f;

    /* ldmatrix source addresses (byte offsets into a buffer) */
    /* A: thread t<16: row=t, k+=0 ; t>=16: row=t-16, k+=8 */
    const uint32_t aRow = (lane & 15);
    const uint32_t aKof = (lane >> 4) * 8;
    /* B: row = (lane&7) + (lane>>4)*8 ; k += ((lane>>3)&1)*8 */
    const uint32_t bRow = (lane & 7) + ((lane >> 4) << 3);
    const uint32_t bKof = ((lane >> 3) & 1) * 8;

    auto issue_stage = [&](int vk, int buf) {
        const int term = vk >> 3;
        const int k0   = (vk & 7) * 32;
        const __nv_bfloat16* As = Asrc[term];
        const __nv_bfloat16* Bs = Bsrc[term];
        const uint32_t da = sA0 + buf * bufBytes;
        const uint32_t db = sB0 + buf * bufBytes;
#pragma unroll
        for (int r = 0; r < 2; r++) {
            int c   = tid + r * 256;
            int row = c >> 2;
            int k16 = c & 3;
            uint32_t so = (uint32_t)(row * LDS + k16 * 8) * 2;
            cp_async16(da + so, As + (size_t)(m0 + row) * DIN + k0 + k16 * 8);
            cp_async16(db + so, Bs + (size_t)(n0 + row) * DIN + k0 + k16 * 8);
        }
        cp_commit();
    };

    issue_stage(0, 0);

#pragma unroll 1
    for (int vk = 0; vk < NVK; vk++) {
        cp_wait0();
        __syncthreads();
        if (vk + 1 < NVK) issue_stage(vk + 1, (vk + 1) & 1);

        const uint32_t ba = sA0 + (vk & 1) * bufBytes;
        const uint32_t bb = sB0 + (vk & 1) * bufBytes;

#pragma unroll
        for (int ks = 0; ks < 2; ks++) {
            const uint32_t kbase = ks * 16;
            uint32_t afr[4][4];
#pragma unroll
            for (int i = 0; i < 4; i++) {
                uint32_t row = wm * 64 + i * 16 + aRow;
                uint32_t addr = ba + (row * LDS + kbase + aKof) * 2;
                ldm_x4(afr[i][0], afr[i][1], afr[i][2], afr[i][3], addr);
            }
            uint32_t bfr[2][4];
#pragma unroll
            for (int q = 0; q < 2; q++) {
                uint32_t row = wn * 32 + q * 16 + bRow;
                uint32_t addr = bb + (row * LDS + kbase + bKof) * 2;
                ldm_x4(bfr[q][0], bfr[q][1], bfr[q][2], bfr[q][3], addr);
            }
#pragma unroll
            for (int i = 0; i < 4; i++)
#pragma unroll
                for (int j = 0; j < 4; j++)
                    mma16816(acc[i][j], afr[i], &bfr[j >> 1][(j & 1) * 2]);
        }
        __syncthreads();
    }

    /* Epilogue: bias + activation, time-major gate write */
    const int gate = blockIdx.x >> 2;              /* 4 n-blocks per gate */
    const float* bias = (gate == 0) ? bi : (gate == 1) ? bfp : (gate == 2) ? bo : bz;
    float* outg = (gate == 0) ? g_gi : (gate == 1) ? g_gf : (gate == 2) ? g_go : g_gz;
    const int hblk = (blockIdx.x & 3) * 128;       /* h offset within gate */

#pragma unroll
    for (int i = 0; i < 4; i++) {
#pragma unroll
        for (int hh = 0; hh < 2; hh++) {
            int m = m0 + wm * 64 + i * 16 + (lane >> 2) + hh * 8;
            int b = m >> 12;
            int s = m & 4095;
            float* op = outg + (size_t)s * NCH + (size_t)b * DH;
#pragma unroll
            for (int j = 0; j < 4; j++) {
                int hcol = hblk + wn * 32 + j * 8 + (lane & 3) * 2;
                float v0 = acc[i][j][hh * 2 + 0] + bias[hcol + 0];
                float v1 = acc[i][j][hh * 2 + 1] + bias[hcol + 1];
                float r0, r1;
                if (gate <= 1) {
                    r0 = __expf(fminf(fmaxf(v0, -20.f), 0.f));
                    r1 = __expf(fminf(fmaxf(v1, -20.f), 0.f));
                } else if (gate == 2) {
                    r0 = 1.f / (1.f + __expf(-v0));
                    r1 = 1.f / (1.f + __expf(-v1));
                } else {
                    r0 = tanhf(v0);
                    r1 = tanhf(v1);
                }
                float2 wv = make_float2(r0, r1);
                *(float2*)(op + hcol) = wv;
            }
        }
    }
}

/* ------------------------------------------------------------------ */
/* Scan (unchanged)                                                    */
/* ------------------------------------------------------------------ */
__global__ __launch_bounds__(128) void scan_passA()
{
    const int ch  = blockIdx.x * 128 + threadIdx.x;
    const int seg = blockIdx.y;
    const size_t off = (size_t)seg * TSEG * NCH + ch;
    const float* pf = g_gf + off;
    const float* pi = g_gi + off;
    const float* pz = g_gz + off;

    float A = 1.f, Bc = 0.f, Bn = 0.f;
#pragma unroll 1
    for (int t = 0; t < TSEG; t += 8) {
        float fv[8], iv[8], zv[8];
#pragma unroll
        for (int u = 0; u < 8; u++) {
            size_t idx = (size_t)(t + u) * NCH;
            fv[u] = pf[idx]; iv[u] = pi[idx]; zv[u] = pz[idx];
        }
#pragma unroll
        for (int u = 0; u < 8; u++) {
            Bc = fmaf(fv[u], Bc, iv[u] * zv[u]);
            Bn = fmaf(fv[u], Bn, iv[u]);
            A  = A * fv[u];
        }
    }
    g_A [(size_t)seg * NCH + ch] = A;
    g_Bc[(size_t)seg * NCH + ch] = Bc;
    g_Bn[(size_t)seg * NCH + ch] = Bn;
}

__global__ __launch_bounds__(128) void scan_passB()
{
    const int ch = blockIdx.x * 128 + threadIdx.x;
    float c = 0.f, n = 1.f;
#pragma unroll 1
    for (int sg = 0; sg < NSEG; sg++) {
        size_t idx = (size_t)sg * NCH + ch;
        g_Cs[idx] = c;
        g_Ns[idx] = n;
        float A  = g_A[idx];
        float Bc = g_Bc[idx];
        float Bn = g_Bn[idx];
        c = fmaf(A, c, Bc);
        n = fmaf(A, n, Bn);
    }
}

__global__ __launch_bounds__(128) void scan_passC(float* __restrict__ out)
{
    const int ch  = blockIdx.x * 128 + threadIdx.x;
    const int seg = blockIdx.y;
    const int b = ch >> 9;
    const int h = ch & 511;

    const size_t off = (size_t)seg * TSEG * NCH + ch;
    const float* pf = g_gf + off;
    const float* pi = g_gi + off;
    const float* po = g_go + off;
    const float* pz = g_gz + off;
    float* op = out + ((size_t)b * S_LEN + (size_t)seg * TSEG) * DH + h;

    size_t sidx = (size_t)seg * NCH + ch;
    float c = g_Cs[sidx];
    float n = g_Ns[sidx];

#pragma unroll 1
    for (int t = 0; t < TSEG; t += 8) {
        float fv[8], iv[8], ov[8], zv[8];
#pragma unroll
        for (int u = 0; u < 8; u++) {
            size_t idx = (size_t)(t + u) * NCH;
            fv[u] = pf[idx]; iv[u] = pi[idx]; ov[u] = po[idx]; zv[u] = pz[idx];
        }
#pragma unroll
        for (int u = 0; u < 8; u++) {
            c = fmaf(fv[u], c, iv[u] * zv[u]);
            n = fmaf(fv[u], n, iv[u]);
            op[(size_t)(t + u) * DH] = ov[u] * c / (n + 1e-6f);
        }
    }
}

/* ------------------------------------------------------------------ */
extern "C" void kernel_launch(void* const* d_in, const int* in_sizes, int n_in,
                              void* d_out, int out_size)
{
    const float* x  = (const float*)d_in[0];
    const float* Wi = (const float*)d_in[1];
    const float* bi = (const float*)d_in[2];
    const float* Wf = (const float*)d_in[3];
    const float* bf = (const float*)d_in[4];
    const float* Wo = (const float*)d_in[5];
    const float* bo = (const float*)d_in[6];
    const float* Wz = (const float*)d_in[7];
    const float* bz = (const float*)d_in[8];
    float* out = (float*)d_out;

    convert_x<<<(MROWS * DIN / 4) / 256, 256>>>(x);
    convert_w<<<dim3(DIN / 32, DH / 32, 4), dim3(32, 8)>>>(Wi, Wf, Wo, Wz);

    gemm_hmma<<<dim3(NTOT / 128, MROWS / 128), 256>>>(bi, bf, bo, bz);

    dim3 gA(NCH / 128, NSEG);
    scan_passA<<<gA, 128>>>();
    scan_passB<<<NCH / 128, 128>>>();
    scan_passC<<<gA, 128>>>(out);
}